// round 5
// baseline (speedup 1.0000x reference)
#include <cuda_runtime.h>
#include <math.h>

// ---------------- problem constants ----------------
#define B_TOK 16384
#define H     1024
#define P2    64      // 2P
#define NE    8
#define EC    32      // E*C pilots
#define NSLOT (2*B_TOK)

// ---------------- device scratch (static; no allocations allowed) ----------------
__device__ float g_x[B_TOK * H];          // layernorm output
__device__ float g_q[B_TOK * H];          // qproj output, then l2-normalized in place
__device__ float g_pn[EC * H];            // normalized pilots
__device__ int   g_te[B_TOK * 2];         // top-2 expert ids per token
__device__ float g_tw[B_TOK * 2];         // top-2 weights per token
__device__ int   g_counts[NE];
__device__ int   g_base[NE];
__device__ int   g_cursor[NE];
__device__ int   g_tokmap[NSLOT];
__device__ float g_wmap[NSLOT];
__device__ float g_hh[(NSLOT + 64) * H];  // expert layer-1 activations (post-relu)
__device__ float g_sh[B_TOK * H];         // shared expert layer-1 activations
__device__ float g_routed[B_TOK * P2];
__device__ float g_sharedout[B_TOK * P2];

// ---------------- reset ----------------
__global__ void reset_kernel() {
    int idx = blockIdx.x * blockDim.x + threadIdx.x;
    if (idx < B_TOK * P2) g_routed[idx] = 0.0f;
    if (idx < NE) g_counts[idx] = 0;
}

// ---------------- layernorm (warp per row) ----------------
__global__ void ln_kernel(const float* __restrict__ mm,
                          const float* __restrict__ gamma,
                          const float* __restrict__ beta) {
    int warp = (blockIdx.x * blockDim.x + threadIdx.x) >> 5;
    int lane = threadIdx.x & 31;
    if (warp >= B_TOK) return;
    const float* row = mm + (size_t)warp * H;
    float s = 0.f, s2 = 0.f;
    for (int i = lane; i < H; i += 32) { float v = row[i]; s += v; s2 += v * v; }
    for (int o = 16; o; o >>= 1) {
        s  += __shfl_xor_sync(0xffffffff, s, o);
        s2 += __shfl_xor_sync(0xffffffff, s2, o);
    }
    float mean = s * (1.0f / H);
    float var  = s2 * (1.0f / H) - mean * mean;
    float inv  = rsqrtf(var + 1e-5f);
    float* out = g_x + (size_t)warp * H;
    for (int i = lane; i < H; i += 32)
        out[i] = (row[i] - mean) * inv * gamma[i] + beta[i];
}

// ---------------- pilot l2 normalize (warp per pilot, 32 pilots) ----------------
__global__ void pilot_norm_kernel(const float* __restrict__ pe) {
    int warp = threadIdx.x >> 5;
    int lane = threadIdx.x & 31;
    const float* row = pe + (size_t)warp * H;
    float s2 = 0.f;
    for (int i = lane; i < H; i += 32) { float v = row[i]; s2 += v * v; }
    for (int o = 16; o; o >>= 1) s2 += __shfl_xor_sync(0xffffffff, s2, o);
    float inv = 1.0f / fmaxf(sqrtf(s2), 1e-12f);
    for (int i = lane; i < H; i += 32) g_pn[warp * H + i] = row[i] * inv;
}

// ---------------- l2 normalize q rows in place (warp per row) ----------------
__global__ void l2q_kernel() {
    int warp = (blockIdx.x * blockDim.x + threadIdx.x) >> 5;
    int lane = threadIdx.x & 31;
    if (warp >= B_TOK) return;
    float* row = g_q + (size_t)warp * H;
    float s2 = 0.f;
    for (int i = lane; i < H; i += 32) { float v = row[i]; s2 += v * v; }
    for (int o = 16; o; o >>= 1) s2 += __shfl_xor_sync(0xffffffff, s2, o);
    float inv = 1.0f / fmaxf(sqrtf(s2), 1e-12f);
    for (int i = lane; i < H; i += 32) row[i] *= inv;
}

// ---------------- router: sims, softmax/temp, top2, counts (warp per token) ---
__global__ void router_kernel() {
    int warp = (blockIdx.x * blockDim.x + threadIdx.x) >> 5;
    int lane = threadIdx.x & 31;
    if (warp >= B_TOK) return;
    const float* q = g_q + (size_t)warp * H;

    float acc[EC];
#pragma unroll
    for (int ec = 0; ec < EC; ec++) acc[ec] = 0.f;

    for (int h = lane; h < H; h += 32) {
        float qv = q[h];
#pragma unroll
        for (int ec = 0; ec < EC; ec++) acc[ec] += qv * g_pn[ec * H + h];
    }

    float sc[NE];
#pragma unroll
    for (int e = 0; e < NE; e++) sc[e] = 0.f;
#pragma unroll
    for (int ec = 0; ec < EC; ec++) {
        float v = acc[ec];
        for (int o = 16; o; o >>= 1) v += __shfl_xor_sync(0xffffffff, v, o);
        sc[ec >> 2] += v * 0.25f;
    }

    // softmax(scores / 0.1)
    float m = -1e30f;
#pragma unroll
    for (int e = 0; e < NE; e++) m = fmaxf(m, sc[e]);
    float p[NE], sum = 0.f;
#pragma unroll
    for (int e = 0; e < NE; e++) { p[e] = expf((sc[e] - m) * 10.f); sum += p[e]; }

    // top-2 on scores (monotone with probs); strict > => lowest index wins ties (jax semantics)
    int i1 = 0;
#pragma unroll
    for (int e = 1; e < NE; e++) if (sc[e] > sc[i1]) i1 = e;
    int i2 = (i1 == 0) ? 1 : 0;
#pragma unroll
    for (int e = 0; e < NE; e++) if (e != i1 && sc[e] > sc[i2]) i2 = e;

    float w1 = p[i1] / sum, w2 = p[i2] / sum;
    float d = w1 + w2 + 1e-6f;
    w1 /= d; w2 /= d;

    if (lane == 0) {
        g_te[warp * 2 + 0] = i1; g_te[warp * 2 + 1] = i2;
        g_tw[warp * 2 + 0] = w1; g_tw[warp * 2 + 1] = w2;
        atomicAdd(&g_counts[i1], 1);
        atomicAdd(&g_counts[i2], 1);
    }
}

// ---------------- scan over 8 experts ----------------
__global__ void scan_kernel() {
    int b = 0;
    for (int e = 0; e < NE; e++) {
        g_base[e] = b;
        g_cursor[e] = b;
        b += g_counts[e];
    }
}

// ---------------- fill compacted assignment lists ----------------
__global__ void fill_kernel() {
    int b = blockIdx.x * blockDim.x + threadIdx.x;
    if (b >= B_TOK) return;
#pragma unroll
    for (int k = 0; k < 2; k++) {
        int e = g_te[b * 2 + k];
        int pos = atomicAdd(&g_cursor[e], 1);
        g_tokmap[pos] = b;
        g_wmap[pos] = g_tw[b * 2 + k];
    }
}

// ================= generic fp32 tiled GEMM: C[M,N] = A[M,K] @ W[K,N] + bias ===
// 64x64 tile, K-tile 16, 256 threads, 4x4 per thread.
template <bool RELU, bool CONCAT>
__global__ __launch_bounds__(256) void gemm_ff(
    const float* __restrict__ A, const float* __restrict__ A2,
    const float* __restrict__ W, const float* __restrict__ bias,
    float* __restrict__ Cmat, int N, int K) {
    __shared__ __align__(16) float As[16][68];
    __shared__ __align__(16) float Bs[16][68];
    int n0 = blockIdx.x * 64, m0 = blockIdx.y * 64;
    int tid = threadIdx.x;
    int ar = tid >> 2, ac = tid & 3;     // A loader: row, k-quad
    int br = tid >> 4, bc = tid & 15;    // W loader: k-row, n-quad
    int tx = tid & 15, ty = tid >> 4;    // compute mapping

    float acc[4][4];
#pragma unroll
    for (int i = 0; i < 4; i++)
#pragma unroll
        for (int j = 0; j < 4; j++) acc[i][j] = 0.f;

    for (int k0 = 0; k0 < K; k0 += 16) {
        int kc = k0 + ac * 4;
        const float* src;
        int lda;
        if (CONCAT) {
            if (kc >= 1024) { src = A2; kc -= 1024; } else src = A;
            lda = 1024;
        } else { src = A; lda = K; }
        float4 av = *(const float4*)&src[(size_t)(m0 + ar) * lda + kc];
        As[ac * 4 + 0][ar] = av.x;
        As[ac * 4 + 1][ar] = av.y;
        As[ac * 4 + 2][ar] = av.z;
        As[ac * 4 + 3][ar] = av.w;
        float4 wv = *(const float4*)&W[(size_t)(k0 + br) * N + n0 + bc * 4];
        *(float4*)&Bs[br][bc * 4] = wv;
        __syncthreads();
#pragma unroll
        for (int k = 0; k < 16; k++) {
            float a[4], b[4];
            *(float4*)a = *(const float4*)&As[k][ty * 4];
            *(float4*)b = *(const float4*)&Bs[k][tx * 4];
#pragma unroll
            for (int i = 0; i < 4; i++)
#pragma unroll
                for (int j = 0; j < 4; j++) acc[i][j] += a[i] * b[j];
        }
        __syncthreads();
    }
#pragma unroll
    for (int i = 0; i < 4; i++) {
        int r = m0 + ty * 4 + i;
#pragma unroll
        for (int j = 0; j < 4; j++) {
            int c = n0 + tx * 4 + j;
            float v = acc[i][j] + bias[c];
            if (RELU) v = fmaxf(v, 0.f);
            Cmat[(size_t)r * N + c] = v;
        }
    }
}

// ================= expert layer-1: hh[slot,1024] = relu(x[tok] @ eW1[e] + eb1[e])
__global__ __launch_bounds__(256) void gemm_e1(const float* __restrict__ eW1,
                                               const float* __restrict__ eb1) {
    __shared__ __align__(16) float As[16][68];
    __shared__ __align__(16) float Bs[16][68];
    int e = blockIdx.z;
    int cnt = g_counts[e];
    int m0 = blockIdx.y * 64;
    if (m0 >= cnt) return;
    int base = g_base[e];
    int n0 = blockIdx.x * 64;
    int tid = threadIdx.x;
    int ar = tid >> 2, ac = tid & 3;
    int br = tid >> 4, bc = tid & 15;
    int tx = tid & 15, ty = tid >> 4;

    int ridx = m0 + ar; if (ridx > cnt - 1) ridx = cnt - 1;
    const float* Arow = g_x + (size_t)g_tokmap[base + ridx] * H;
    const float* W = eW1 + (size_t)e * H * H;

    float acc[4][4];
#pragma unroll
    for (int i = 0; i < 4; i++)
#pragma unroll
        for (int j = 0; j < 4; j++) acc[i][j] = 0.f;

    for (int k0 = 0; k0 < H; k0 += 16) {
        float4 av = *(const float4*)&Arow[k0 + ac * 4];
        As[ac * 4 + 0][ar] = av.x;
        As[ac * 4 + 1][ar] = av.y;
        As[ac * 4 + 2][ar] = av.z;
        As[ac * 4 + 3][ar] = av.w;
        float4 wv = *(const float4*)&W[(size_t)(k0 + br) * H + n0 + bc * 4];
        *(float4*)&Bs[br][bc * 4] = wv;
        __syncthreads();
#pragma unroll
        for (int k = 0; k < 16; k++) {
            float a[4], b[4];
            *(float4*)a = *(const float4*)&As[k][ty * 4];
            *(float4*)b = *(const float4*)&Bs[k][tx * 4];
#pragma unroll
            for (int i = 0; i < 4; i++)
#pragma unroll
                for (int j = 0; j < 4; j++) acc[i][j] += a[i] * b[j];
        }
        __syncthreads();
    }
#pragma unroll
    for (int i = 0; i < 4; i++) {
        int r = ty * 4 + i;
        if (m0 + r < cnt) {
            int slot = base + m0 + r;
#pragma unroll
            for (int j = 0; j < 4; j++) {
                int c = n0 + tx * 4 + j;
                float v = acc[i][j] + eb1[e * H + c];
                g_hh[(size_t)slot * H + c] = fmaxf(v, 0.f);
            }
        }
    }
}

// ================= expert layer-2: routed[tok] += w * (hh[slot] @ eW2[e] + eb2[e])
__global__ __launch_bounds__(256) void gemm_e2(const float* __restrict__ eW2,
                                               const float* __restrict__ eb2) {
    __shared__ __align__(16) float As[16][68];
    __shared__ __align__(16) float Bs[16][68];
    int e = blockIdx.z;
    int cnt = g_counts[e];
    int m0 = blockIdx.y * 64;
    if (m0 >= cnt) return;
    int base = g_base[e];
    int tid = threadIdx.x;
    int ar = tid >> 2, ac = tid & 3;
    int br = tid >> 4, bc = tid & 15;
    int tx = tid & 15, ty = tid >> 4;

    int ridx = m0 + ar; if (ridx > cnt - 1) ridx = cnt - 1;
    const float* Arow = g_hh + (size_t)(base + ridx) * H;
    const float* W = eW2 + (size_t)e * H * P2;

    float acc[4][4];
#pragma unroll
    for (int i = 0; i < 4; i++)
#pragma unroll
        for (int j = 0; j < 4; j++) acc[i][j] = 0.f;

    for (int k0 = 0; k0 < H; k0 += 16) {
        float4 av = *(const float4*)&Arow[k0 + ac * 4];
        As[ac * 4 + 0][ar] = av.x;
        As[ac * 4 + 1][ar] = av.y;
        As[ac * 4 + 2][ar] = av.z;
        As[ac * 4 + 3][ar] = av.w;
        float4 wv = *(const float4*)&W[(size_t)(k0 + br) * P2 + bc * 4];
        *(float4*)&Bs[br][bc * 4] = wv;
        __syncthreads();
#pragma unroll
        for (int k = 0; k < 16; k++) {
            float a[4], b[4];
            *(float4*)a = *(const float4*)&As[k][ty * 4];
            *(float4*)b = *(const float4*)&Bs[k][tx * 4];
#pragma unroll
            for (int i = 0; i < 4; i++)
#pragma unroll
                for (int j = 0; j < 4; j++) acc[i][j] += a[i] * b[j];
        }
        __syncthreads();
    }
#pragma unroll
    for (int i = 0; i < 4; i++) {
        int r = ty * 4 + i;
        if (m0 + r < cnt) {
            int slot = base + m0 + r;
            int tok = g_tokmap[slot];
            float w = g_wmap[slot];
#pragma unroll
            for (int j = 0; j < 4; j++) {
                int c = tx * 4 + j;
                float v = acc[i][j] + eb2[e * P2 + c];
                atomicAdd(&g_routed[(size_t)tok * P2 + c], w * v);
            }
        }
    }
}

// ---------------- final gate + sigmoid (warp per token) ----------------
__global__ __launch_bounds__(256) void gate_kernel(const float* __restrict__ gW,
                                                   const float* __restrict__ gb,
                                                   float* __restrict__ out) {
    __shared__ __align__(16) float sW[128 * 64];  // 32KB
    for (int i = threadIdx.x; i < 128 * 64 / 4; i += 256)
        *(float4*)&sW[i * 4] = *(const float4*)&gW[i * 4];
    __syncthreads();
    int warp = threadIdx.x >> 5;
    int lane = threadIdx.x & 31;
    int tok = blockIdx.x * 8 + warp;
    if (tok >= B_TOK) return;
    const float* r = g_routed + (size_t)tok * P2;
    const float* s = g_sharedout + (size_t)tok * P2;
    float a0 = gb[lane], a1 = gb[lane + 32];
#pragma unroll 8
    for (int k = 0; k < 64; k++) {
        float c = r[k];
        a0 += c * sW[k * 64 + lane];
        a1 += c * sW[k * 64 + lane + 32];
    }
#pragma unroll 8
    for (int k = 0; k < 64; k++) {
        float c = s[k];
        a0 += c * sW[(64 + k) * 64 + lane];
        a1 += c * sW[(64 + k) * 64 + lane + 32];
    }
    out[(size_t)tok * P2 + lane]      = 1.0f / (1.0f + expf(-a0));
    out[(size_t)tok * P2 + lane + 32] = 1.0f / (1.0f + expf(-a1));
}

// ---------------- host launch sequence ----------------
extern "C" void kernel_launch(void* const* d_in, const int* in_sizes, int n_in,
                              void* d_out, int out_size) {
    const float* mm   = (const float*)d_in[0];
    const float* qf   = (const float*)d_in[1];
    const float* lng  = (const float*)d_in[2];
    const float* lnb  = (const float*)d_in[3];
    const float* pe   = (const float*)d_in[4];
    const float* qW   = (const float*)d_in[5];
    const float* qb   = (const float*)d_in[6];
    const float* eW1  = (const float*)d_in[7];
    const float* eb1  = (const float*)d_in[8];
    const float* eW2  = (const float*)d_in[9];
    const float* eb2  = (const float*)d_in[10];
    const float* sW1  = (const float*)d_in[11];
    const float* sb1  = (const float*)d_in[12];
    const float* sW2  = (const float*)d_in[13];
    const float* sb2  = (const float*)d_in[14];
    const float* gW   = (const float*)d_in[15];
    const float* gb   = (const float*)d_in[16];
    float* out = (float*)d_out;

    float *p_x, *p_q, *p_sh, *p_so;
    cudaGetSymbolAddress((void**)&p_x,  g_x);
    cudaGetSymbolAddress((void**)&p_q,  g_q);
    cudaGetSymbolAddress((void**)&p_sh, g_sh);
    cudaGetSymbolAddress((void**)&p_so, g_sharedout);

    reset_kernel<<<4096, 256>>>();
    ln_kernel<<<B_TOK / 8, 256>>>(mm, lng, lnb);
    pilot_norm_kernel<<<1, 1024>>>(pe);

    // qproj: [B,2048] @ [2048,1024] + b  (A = concat(x, query))
    gemm_ff<false, true><<<dim3(16, 256), 256>>>(p_x, qf, qW, qb, p_q, 1024, 2048);
    l2q_kernel<<<B_TOK / 8, 256>>>();
    router_kernel<<<B_TOK / 8, 256>>>();
    scan_kernel<<<1, 1>>>();
    fill_kernel<<<B_TOK / 256, 256>>>();

    // routed experts (sparse, per-expert segments)
    gemm_e1<<<dim3(16, B_TOK / 64, NE), 256>>>(eW1, eb1);
    gemm_e2<<<dim3(1, B_TOK / 64, NE), 256>>>(eW2, eb2);

    // shared expert
    gemm_ff<true, false><<<dim3(16, 256), 256>>>(p_x, nullptr, sW1, sb1, p_sh, 1024, 1024);
    gemm_ff<false, false><<<dim3(1, 256), 256>>>(p_sh, nullptr, sW2, sb2, p_so, 64, 1024);

    // gate + sigmoid -> output
    gate_kernel<<<B_TOK / 8, 256>>>(gW, gb, out);
}